// round 6
// baseline (speedup 1.0000x reference)
#include <cuda_runtime.h>
#include <cuda_bf16.h>

#define IMG    256
#define NEARP  0.1f
#define FARP   100.0f
#define CHUNKF 128
#define NTILE  256        // 16x16 tiles of 16x16 px
#define CAP    8192
#define MAXB   2
#define RASTB  1184       // fixed rast grid (148 SMs * 8)

#define MAXV 16384
#define MAXF 32768
#define MAXWORK (MAXB * NTILE * (CAP / CHUNKF))

// Per-vertex screen data: (sx, sy, z_cam, 1/max(z,1e-4))
__device__ float4 g_vs[MAXV];
// Per-face linear coefficients:
//   w0 = A.x + px*A.y + py*A.z ; w1 = A.w + px*B.x + py*B.y
//   inv_z = E + w0*B.z + w1*B.w
__device__ float4 g_fA[MAXF];
__device__ float4 g_fB[MAXF];
__device__ float  g_fE[MAXF];
// Tile binning
__device__ int      g_cnt[MAXB * NTILE];
__device__ int      g_list[MAXB * NTILE * CAP];
// Work items: (tileIdx | chunk<<16)
__device__ int      g_work[MAXWORK];
__device__ int      g_nwork;
// Per-pixel running max(inv_z) as uint bit pattern (valid: nonneg floats)
__device__ unsigned g_best[MAXB * IMG * IMG];

// ---------------------------------------------------------------------------
// Kernel 1: clear buffers + vertex transform (fused).
// look_at collapses to diag(1,1,zn); then perspective.
// ---------------------------------------------------------------------------
__global__ void init_k(const float* __restrict__ v, int nvt, int npx, int ncnt)
{
    int i = blockIdx.x * blockDim.x + threadIdx.x;
    if (i < npx)  g_best[i] = 0u;
    if (i < ncnt) g_cnt[i]  = 0;
    if (i >= nvt) return;
    const float ez  = 2.7320508075688772f;   // 1/tan(30deg) + 1
    const float wdt = 0.57735026918962576f;  // tan(30deg)
    float zn = ez / sqrtf(ez * ez);          // replicate ref's normalize rounding
    float vx = v[3 * i + 0];
    float vy = v[3 * i + 1];
    float vz = v[3 * i + 2];
    float z  = (vz + ez) * zn;
    float zs = (fabsf(z) < 1e-5f) ? 1e-5f : z;
    float sx = vx / (zs * wdt);
    float sy = vy / (zs * wdt);
    float zc = fmaxf(z, 1e-4f);
    g_vs[i] = make_float4(sx, sy, z, 1.0f / zc);
}

// Max of linear form a + b*x + c*y over rect [x0,x1]x[y0,y1]
__device__ __forceinline__ float lin_max(float a, float b, float c,
                                         float x0, float x1, float y0, float y1)
{
    return a + b * (b > 0.0f ? x1 : x0) + c * (c > 0.0f ? y1 : y0);
}

// ---------------------------------------------------------------------------
// Kernel 2: face setup + tile binning with conservative tri-tile cull.
// fill_back duplicates are coverage/depth-identical, so only NF originals.
// ---------------------------------------------------------------------------
__global__ void face_k(const int* __restrict__ faces, int nf, int nv, int B)
{
    int f = blockIdx.x * blockDim.x + threadIdx.x;
    if (f >= nf * B) return;
    int b = f / nf;
    int i0 = faces[3 * f + 0];
    int i1 = faces[3 * f + 1];
    int i2 = faces[3 * f + 2];
    float4 p0 = g_vs[b * nv + i0];
    float4 p1 = g_vs[b * nv + i1];
    float4 p2 = g_vs[b * nv + i2];

    bool ok = (p0.z > NEARP) && (p1.z > NEARP) && (p2.z > NEARP);
    float area = (p1.x - p0.x) * (p2.y - p0.y) - (p2.x - p0.x) * (p1.y - p0.y);
    ok = ok && (fabsf(area) > 1e-8f);
    if (!ok) return;

    // Conservative pixel bbox (+-1 px). px(ix) = (2ix+1-256)/256.
    float xmin = fminf(p0.x, fminf(p1.x, p2.x));
    float xmax = fmaxf(p0.x, fmaxf(p1.x, p2.x));
    float ymin = fminf(p0.y, fminf(p1.y, p2.y));
    float ymax = fmaxf(p0.y, fmaxf(p1.y, p2.y));
    int ixlo = (int)floorf(xmin * 128.0f + 127.5f) - 1;
    int ixhi = (int)floorf(xmax * 128.0f + 127.5f) + 1;
    int iylo = (int)floorf(ymin * 128.0f + 127.5f) - 1;
    int iyhi = (int)floorf(ymax * 128.0f + 127.5f) + 1;
    if (ixhi < 0 || ixlo > IMG - 1 || iyhi < 0 || iylo > IMG - 1) return;
    ixlo = max(ixlo, 0); ixhi = min(ixhi, IMG - 1);
    iylo = max(iylo, 0); iyhi = min(iyhi, IMG - 1);

    if (area < 0.0f) {  // swap v1<->v2: same barycentric set, positive area
        float4 t = p1; p1 = p2; p2 = t;
        area = -area;
    }
    float ia = 1.0f / area;
    float a0 = (p1.x * p2.y - p2.x * p1.y) * ia;
    float b0 = (p1.y - p2.y) * ia;
    float c0 = (p2.x - p1.x) * ia;
    float a1 = (p2.x * p0.y - p0.x * p2.y) * ia;
    float b1 = (p2.y - p0.y) * ia;
    float c1 = (p0.x - p2.x) * ia;
    float d0 = p0.w - p2.w;
    float d1 = p1.w - p2.w;
    g_fA[f] = make_float4(a0, b0, c0, a1);
    g_fB[f] = make_float4(b1, c1, d0, d1);
    g_fE[f] = p2.w;
    // w2 = 1 - w0 - w1 as a linear form
    float a2 = 1.0f - a0 - a1;
    float b2 = -b0 - b1;
    float c2 = -c0 - c1;

    float e0 = 1e-5f * (fabsf(a0) + fabsf(b0) + fabsf(c0));
    float e1 = 1e-5f * (fabsf(a1) + fabsf(b1) + fabsf(c1));
    float e2 = 1e-5f * (fabsf(a2) + fabsf(b2) + fabsf(c2));

    int tx0 = ixlo >> 4, tx1 = ixhi >> 4;
    int ty0 = iylo >> 4, ty1 = iyhi >> 4;
    for (int ty = ty0; ty <= ty1; ++ty) {
        float ry0 = (float)(2 * (ty << 4) + 1 - IMG) * (1.0f / IMG) - (2.0f / IMG);
        float ry1 = (float)(2 * ((ty << 4) + 15) + 1 - IMG) * (1.0f / IMG) + (2.0f / IMG);
        for (int tx = tx0; tx <= tx1; ++tx) {
            float rx0 = (float)(2 * (tx << 4) + 1 - IMG) * (1.0f / IMG) - (2.0f / IMG);
            float rx1 = (float)(2 * ((tx << 4) + 15) + 1 - IMG) * (1.0f / IMG) + (2.0f / IMG);
            if (lin_max(a0, b0, c0, rx0, rx1, ry0, ry1) < -e0) continue;
            if (lin_max(a1, b1, c1, rx0, rx1, ry0, ry1) < -e1) continue;
            if (lin_max(a2, b2, c2, rx0, rx1, ry0, ry1) < -e2) continue;
            int t = b * NTILE + ty * 16 + tx;
            int pos = atomicAdd(&g_cnt[t], 1);
            if (pos < CAP) g_list[t * CAP + pos] = f;
        }
    }
}

// ---------------------------------------------------------------------------
// Kernel 3: scheduler. One block, 256 threads: turn per-tile counts into a
// compact work-item list (tile | chunk<<16) via block-wide exclusive scan.
// ---------------------------------------------------------------------------
__global__ void __launch_bounds__(256) sched_k(int B)
{
    __shared__ int warp_sums[8];
    int tid  = threadIdx.x;
    int lane = tid & 31;
    int wid  = tid >> 5;
    int total = 0;

    for (int b = 0; b < B; ++b) {
        int t = b * NTILE + tid;
        int n = min(g_cnt[t], CAP);
        int nch = (n + CHUNKF - 1) / CHUNKF;

        // inclusive scan within warp
        int v = nch;
        #pragma unroll
        for (int o = 1; o < 32; o <<= 1) {
            int u = __shfl_up_sync(0xFFFFFFFFu, v, o);
            if (lane >= o) v += u;
        }
        if (lane == 31) warp_sums[wid] = v;
        __syncthreads();
        int wbase = 0;
        if (wid == 0 && lane < 8) {
            int s = warp_sums[lane];
            #pragma unroll
            for (int o = 1; o < 8; o <<= 1) {
                int u = __shfl_up_sync(0xFFu, s, o);
                if (lane >= o) s += u;
            }
            warp_sums[lane] = s;   // inclusive over warps
        }
        __syncthreads();
        if (wid > 0) wbase = warp_sums[wid - 1];
        int excl = total + wbase + (v - nch);
        for (int c = 0; c < nch; ++c)
            g_work[excl + c] = t | (c << 16);
        total += warp_sums[7];
        __syncthreads();
    }
    if (tid == 0) g_nwork = total;
}

// ---------------------------------------------------------------------------
// Kernel 4: rasterize. Fixed grid; blocks grid-stride over work items.
// 128 threads; thread owns pixels (ix,iy) and (ix,iy+8) of the 16x16 tile.
// Partial maxima merge via atomicMax on inv_z bits (order-invariant).
// ---------------------------------------------------------------------------
__global__ void __launch_bounds__(128) rast_k(void)
{
    __shared__ float4 sA[CHUNKF];
    __shared__ float4 sB[CHUNKF];
    __shared__ float  sE[CHUNKF];

    int tid = threadIdx.x;
    int nwork = g_nwork;

    for (int w = blockIdx.x; w < nwork; w += gridDim.x) {
        int item  = g_work[w];
        int t     = item & 0xFFFF;          // b*NTILE + tile
        int chunk = item >> 16;
        int b     = t >> 8;
        int tile  = t & (NTILE - 1);

        int n = min(g_cnt[t], CAP);
        int c0 = chunk * CHUNKF;
        int m = min(CHUNKF, n - c0);

        int ix = ((tile & 15) << 4) | (tid & 15);
        int iy = ((tile >> 4) << 4) | (tid >> 4);   // +0..7
        float px = (float)(2 * ix + 1 - IMG) * (1.0f / IMG);
        float py = (float)(2 * iy + 1 - IMG) * (1.0f / IMG);
        const float DY = 16.0f / IMG;

        if (tid < m) {
            int f = g_list[t * CAP + c0 + tid];
            sA[tid] = g_fA[f];
            sB[tid] = g_fB[f];
            sE[tid] = g_fE[f];
        }
        __syncthreads();

        float best0 = 0.0f, best1 = 0.0f;
        #pragma unroll 4
        for (int j = 0; j < m; ++j) {
            float4 A  = sA[j];
            float4 Bv = sB[j];
            float  e  = sE[j];
            float w0 = fmaf(py, A.z,  fmaf(px, A.y,  A.x));
            float w1 = fmaf(py, Bv.y, fmaf(px, Bv.x, A.w));
            float w2 = 1.0f - w0 - w1;
            float iz = fmaf(w1, Bv.w, fmaf(w0, Bv.z, e));
            bool ok  = (fminf(fminf(w0, w1), w2) >= 0.0f) &&
                       (iz > 0.01f) && (iz < 10.0f);
            best0 = fmaxf(best0, ok ? iz : 0.0f);

            float w0b = fmaf(DY, A.z,  w0);
            float w1b = fmaf(DY, Bv.y, w1);
            float w2b = 1.0f - w0b - w1b;
            float izb = fmaf(w1b, Bv.w, fmaf(w0b, Bv.z, e));
            bool okb  = (fminf(fminf(w0b, w1b), w2b) >= 0.0f) &&
                        (izb > 0.01f) && (izb < 10.0f);
            best1 = fmaxf(best1, okb ? izb : 0.0f);
        }

        unsigned* bb = &g_best[b * (IMG * IMG)];
        if (best0 > 0.0f) atomicMax(&bb[iy * IMG + ix],       __float_as_uint(best0));
        if (best1 > 0.0f) atomicMax(&bb[(iy + 8) * IMG + ix], __float_as_uint(best1));
        __syncthreads();
    }
}

// ---------------------------------------------------------------------------
// Kernel 5: convert max(inv_z) -> depth. Vectorized 4 px/thread.
// ---------------------------------------------------------------------------
__global__ void final_k(float* __restrict__ out, int npx4)
{
    int i = blockIdx.x * blockDim.x + threadIdx.x;
    if (i >= npx4) return;
    uint4 u = ((const uint4*)g_best)[i];
    float4 r;
    r.x = (u.x > 0u) ? (1.0f / __uint_as_float(u.x)) : FARP;
    r.y = (u.y > 0u) ? (1.0f / __uint_as_float(u.y)) : FARP;
    r.z = (u.z > 0u) ? (1.0f / __uint_as_float(u.z)) : FARP;
    r.w = (u.w > 0u) ? (1.0f / __uint_as_float(u.w)) : FARP;
    ((float4*)out)[i] = r;
}

// ---------------------------------------------------------------------------
extern "C" void kernel_launch(void* const* d_in, const int* in_sizes, int n_in,
                              void* d_out, int out_size)
{
    const float* verts = (const float*)d_in[0];
    const int*   faces = (const int*)d_in[1];
    float*       out   = (float*)d_out;

    int B = out_size / (IMG * IMG);
    if (B < 1) B = 1;
    int nv = in_sizes[0] / (3 * B);
    int nf = in_sizes[1] / (3 * B);
    int nvt = B * nv;
    int nft = B * nf;
    int npx = B * IMG * IMG;

    int initN = npx > nvt ? npx : nvt;
    init_k<<<(initN + 255) / 256, 256>>>(verts, nvt, npx, B * NTILE);
    face_k<<<(nft + 255) / 256, 256>>>(faces, nf, nv, B);
    sched_k<<<1, 256>>>(B);
    rast_k<<<RASTB, 128>>>();
    final_k<<<(npx / 4 + 255) / 256, 256>>>(out, npx / 4);
}

// round 7
// speedup vs baseline: 1.5157x; 1.5157x over previous
#include <cuda_runtime.h>
#include <cuda_bf16.h>

#define IMG    256
#define NEARP  0.1f
#define FARP   100.0f
#define CHUNKF 64
#define NTILE  256        // 16x16 tiles of 16x16 px
#define CAP    8192
#define MAXB   2
#define RASTB  1184       // fixed rast grid
#define FACE_T 512

#define MAXV 16384
#define MAXF 32768
#define NT_ALL (MAXB * NTILE)           // 512
#define MAXWORK (NT_ALL * (CAP / CHUNKF))

// Per-vertex screen data: (sx, sy, z_cam, 1/max(z,1e-4))
__device__ float4 g_vs[MAXV];
// Per-face linear coefficients:
//   w0 = A.x + px*A.y + py*A.z ; w1 = A.w + px*B.x + py*B.y
//   inv_z = E + w0*B.z + w1*B.w
__device__ float4 g_fA[MAXF];
__device__ float4 g_fB[MAXF];
__device__ float  g_fE[MAXF];
// Tile binning
__device__ int      g_cnt[NT_ALL];
__device__ int      g_list[NT_ALL * CAP];
// Work items: (tileIdx | chunk<<16)
__device__ int      g_work[MAXWORK];
__device__ int      g_nwork;
__device__ int      g_done;
// Per-pixel running max(inv_z) as uint bit pattern (valid: nonneg floats)
__device__ unsigned g_best[MAXB * IMG * IMG];

// ---------------------------------------------------------------------------
// Kernel 1: clear buffers + vertex transform (fused).
// look_at collapses to diag(1,1,zn); then perspective.
// ---------------------------------------------------------------------------
__global__ void init_k(const float* __restrict__ v, int nvt, int npx4)
{
    int i = blockIdx.x * blockDim.x + threadIdx.x;
    if (i < npx4) ((uint4*)g_best)[i] = make_uint4(0u, 0u, 0u, 0u);
    if (i < NT_ALL) g_cnt[i] = 0;
    if (i == 0) { g_done = 0; g_nwork = 0; }
    if (i >= nvt) return;
    const float ez  = 2.7320508075688772f;   // 1/tan(30deg) + 1
    const float wdt = 0.57735026918962576f;  // tan(30deg)
    float zn = ez / sqrtf(ez * ez);          // replicate ref's normalize rounding
    float vx = v[3 * i + 0];
    float vy = v[3 * i + 1];
    float vz = v[3 * i + 2];
    float z  = (vz + ez) * zn;
    float zs = (fabsf(z) < 1e-5f) ? 1e-5f : z;
    float sx = vx / (zs * wdt);
    float sy = vy / (zs * wdt);
    float zc = fmaxf(z, 1e-4f);
    g_vs[i] = make_float4(sx, sy, z, 1.0f / zc);
}

// Max of linear form a + b*x + c*y over rect [x0,x1]x[y0,y1]
__device__ __forceinline__ float lin_max(float a, float b, float c,
                                         float x0, float x1, float y0, float y1)
{
    return a + b * (b > 0.0f ? x1 : x0) + c * (c > 0.0f ? y1 : y0);
}

// ---------------------------------------------------------------------------
// Kernel 2: face setup + binning with smem-privatized counters (3 phases),
// then the LAST block (ticket on g_done) builds the compact work-item list.
// fill_back duplicates are coverage/depth-identical, so only NF originals.
// ---------------------------------------------------------------------------
__global__ void __launch_bounds__(FACE_T) face_k(const int* __restrict__ faces,
                                                 int nf, int nv, int B)
{
    __shared__ int s_cnt[NT_ALL];
    __shared__ int s_base[NT_ALL];
    __shared__ int s_wsum[16];
    __shared__ int s_islast;

    int tid = threadIdx.x;
    for (int i = tid; i < NT_ALL; i += FACE_T) s_cnt[i] = 0;
    __syncthreads();

    int f = blockIdx.x * FACE_T + tid;
    bool active = (f < nf * B);

    float a0=0,b0=0,c0=0,a1=0,b1=0,c1=0,a2=0,b2=0,c2=0,e0=0,e1=0,e2=0;
    int tx0=0, tx1=-1, ty0=0, ty1=-1, bb_b = 0;

    if (active) {
        int b = f / nf;
        bb_b = b;
        int i0 = faces[3 * f + 0];
        int i1 = faces[3 * f + 1];
        int i2 = faces[3 * f + 2];
        float4 p0 = g_vs[b * nv + i0];
        float4 p1 = g_vs[b * nv + i1];
        float4 p2 = g_vs[b * nv + i2];

        bool ok = (p0.z > NEARP) && (p1.z > NEARP) && (p2.z > NEARP);
        float area = (p1.x - p0.x) * (p2.y - p0.y) - (p2.x - p0.x) * (p1.y - p0.y);
        ok = ok && (fabsf(area) > 1e-8f);

        if (ok) {
            // Conservative pixel bbox (+-1 px). px(ix) = (2ix+1-256)/256.
            float xmin = fminf(p0.x, fminf(p1.x, p2.x));
            float xmax = fmaxf(p0.x, fmaxf(p1.x, p2.x));
            float ymin = fminf(p0.y, fminf(p1.y, p2.y));
            float ymax = fmaxf(p0.y, fmaxf(p1.y, p2.y));
            int ixlo = (int)floorf(xmin * 128.0f + 127.5f) - 1;
            int ixhi = (int)floorf(xmax * 128.0f + 127.5f) + 1;
            int iylo = (int)floorf(ymin * 128.0f + 127.5f) - 1;
            int iyhi = (int)floorf(ymax * 128.0f + 127.5f) + 1;
            if (ixhi < 0 || ixlo > IMG - 1 || iyhi < 0 || iylo > IMG - 1) {
                ok = false;
            } else {
                ixlo = max(ixlo, 0); ixhi = min(ixhi, IMG - 1);
                iylo = max(iylo, 0); iyhi = min(iyhi, IMG - 1);

                if (area < 0.0f) {  // swap v1<->v2: same barycentrics, +area
                    float4 t = p1; p1 = p2; p2 = t;
                    area = -area;
                }
                float ia = 1.0f / area;
                a0 = (p1.x * p2.y - p2.x * p1.y) * ia;
                b0 = (p1.y - p2.y) * ia;
                c0 = (p2.x - p1.x) * ia;
                a1 = (p2.x * p0.y - p0.x * p2.y) * ia;
                b1 = (p2.y - p0.y) * ia;
                c1 = (p0.x - p2.x) * ia;
                float d0 = p0.w - p2.w;
                float d1 = p1.w - p2.w;
                g_fA[f] = make_float4(a0, b0, c0, a1);
                g_fB[f] = make_float4(b1, c1, d0, d1);
                g_fE[f] = p2.w;
                a2 = 1.0f - a0 - a1;
                b2 = -b0 - b1;
                c2 = -c0 - c1;
                e0 = 1e-5f * (fabsf(a0) + fabsf(b0) + fabsf(c0));
                e1 = 1e-5f * (fabsf(a1) + fabsf(b1) + fabsf(c1));
                e2 = 1e-5f * (fabsf(a2) + fabsf(b2) + fabsf(c2));
                tx0 = ixlo >> 4; tx1 = ixhi >> 4;
                ty0 = iylo >> 4; ty1 = iyhi >> 4;
            }
        }
        active = ok;
    }

    // Phase A: count covered tiles into shared counters.
    if (active) {
        for (int ty = ty0; ty <= ty1; ++ty) {
            float ry0 = (float)(2 * (ty << 4) + 1 - IMG) * (1.0f / IMG) - (2.0f / IMG);
            float ry1 = (float)(2 * ((ty << 4) + 15) + 1 - IMG) * (1.0f / IMG) + (2.0f / IMG);
            for (int tx = tx0; tx <= tx1; ++tx) {
                float rx0 = (float)(2 * (tx << 4) + 1 - IMG) * (1.0f / IMG) - (2.0f / IMG);
                float rx1 = (float)(2 * ((tx << 4) + 15) + 1 - IMG) * (1.0f / IMG) + (2.0f / IMG);
                if (lin_max(a0, b0, c0, rx0, rx1, ry0, ry1) < -e0) continue;
                if (lin_max(a1, b1, c1, rx0, rx1, ry0, ry1) < -e1) continue;
                if (lin_max(a2, b2, c2, rx0, rx1, ry0, ry1) < -e2) continue;
                atomicAdd(&s_cnt[bb_b * NTILE + ty * 16 + tx], 1);
            }
        }
    }
    __syncthreads();

    // Phase B: one global reservation per (tile, block).
    for (int i = tid; i < NT_ALL; i += FACE_T) {
        int c = s_cnt[i];
        s_base[i] = (c > 0) ? atomicAdd(&g_cnt[i], c) : 0;
        s_cnt[i] = 0;
    }
    __syncthreads();

    // Phase C: emit entries at reserved offsets.
    if (active) {
        for (int ty = ty0; ty <= ty1; ++ty) {
            float ry0 = (float)(2 * (ty << 4) + 1 - IMG) * (1.0f / IMG) - (2.0f / IMG);
            float ry1 = (float)(2 * ((ty << 4) + 15) + 1 - IMG) * (1.0f / IMG) + (2.0f / IMG);
            for (int tx = tx0; tx <= tx1; ++tx) {
                float rx0 = (float)(2 * (tx << 4) + 1 - IMG) * (1.0f / IMG) - (2.0f / IMG);
                float rx1 = (float)(2 * ((tx << 4) + 15) + 1 - IMG) * (1.0f / IMG) + (2.0f / IMG);
                if (lin_max(a0, b0, c0, rx0, rx1, ry0, ry1) < -e0) continue;
                if (lin_max(a1, b1, c1, rx0, rx1, ry0, ry1) < -e1) continue;
                if (lin_max(a2, b2, c2, rx0, rx1, ry0, ry1) < -e2) continue;
                int t = bb_b * NTILE + ty * 16 + tx;
                int idx = s_base[t] + atomicAdd(&s_cnt[t], 1);
                if (idx < CAP) g_list[t * CAP + idx] = f;
            }
        }
    }

    // Last-block ticket, then build the work list in that block.
    __threadfence();
    __syncthreads();
    if (tid == 0)
        s_islast = (atomicAdd(&g_done, 1) == (int)gridDim.x - 1) ? 1 : 0;
    __syncthreads();
    if (!s_islast) return;

    // Scheduler: 512 threads over 512 tiles; block-wide exclusive scan.
    {
        int lane = tid & 31;
        int wid  = tid >> 5;
        int n    = min(g_cnt[tid], CAP);
        int nch  = (n + CHUNKF - 1) / CHUNKF;
        int v = nch;
        #pragma unroll
        for (int o = 1; o < 32; o <<= 1) {
            int u = __shfl_up_sync(0xFFFFFFFFu, v, o);
            if (lane >= o) v += u;
        }
        if (lane == 31) s_wsum[wid] = v;
        __syncthreads();
        if (wid == 0) {
            int s = (lane < 16) ? s_wsum[lane] : 0;
            #pragma unroll
            for (int o = 1; o < 16; o <<= 1) {
                int u = __shfl_up_sync(0xFFFFFFFFu, s, o);
                if (lane >= o) s += u;
            }
            if (lane < 16) s_wsum[lane] = s;
        }
        __syncthreads();
        int excl = ((wid > 0) ? s_wsum[wid - 1] : 0) + v - nch;
        for (int c = 0; c < nch; ++c)
            g_work[excl + c] = tid | (c << 16);
        if (tid == 0) g_nwork = s_wsum[15];
    }
}

// ---------------------------------------------------------------------------
// Kernel 3: rasterize. Fixed grid; blocks grid-stride over work items.
// 128 threads; thread owns pixels (ix,iy) and (ix,iy+8) of the 16x16 tile.
// Partial maxima merge via atomicMax on inv_z bits (order-invariant).
// ---------------------------------------------------------------------------
__global__ void __launch_bounds__(128) rast_k(void)
{
    __shared__ float4 sA[CHUNKF];
    __shared__ float4 sB[CHUNKF];
    __shared__ float  sE[CHUNKF];

    int tid = threadIdx.x;
    int nwork = g_nwork;

    for (int w = blockIdx.x; w < nwork; w += gridDim.x) {
        int item  = g_work[w];
        int t     = item & 0xFFFF;          // b*NTILE + tile
        int chunk = item >> 16;
        int b     = t >> 8;
        int tile  = t & (NTILE - 1);

        int n = min(g_cnt[t], CAP);
        int c0 = chunk * CHUNKF;
        int m = min(CHUNKF, n - c0);

        int ix = ((tile & 15) << 4) | (tid & 15);
        int iy = ((tile >> 4) << 4) | (tid >> 4);   // +0..7
        float px = (float)(2 * ix + 1 - IMG) * (1.0f / IMG);
        float py = (float)(2 * iy + 1 - IMG) * (1.0f / IMG);
        const float DY = 16.0f / IMG;

        if (tid < m) {
            int f = g_list[t * CAP + c0 + tid];
            sA[tid] = g_fA[f];
            sB[tid] = g_fB[f];
            sE[tid] = g_fE[f];
        }
        __syncthreads();

        float best0 = 0.0f, best1 = 0.0f;
        #pragma unroll 4
        for (int j = 0; j < m; ++j) {
            float4 A  = sA[j];
            float4 Bv = sB[j];
            float  e  = sE[j];
            float w0 = fmaf(py, A.z,  fmaf(px, A.y,  A.x));
            float w1 = fmaf(py, Bv.y, fmaf(px, Bv.x, A.w));
            float w2 = 1.0f - w0 - w1;
            float iz = fmaf(w1, Bv.w, fmaf(w0, Bv.z, e));
            bool ok  = (fminf(fminf(w0, w1), w2) >= 0.0f) &&
                       (iz > 0.01f) && (iz < 10.0f);
            best0 = fmaxf(best0, ok ? iz : 0.0f);

            float w0b = fmaf(DY, A.z,  w0);
            float w1b = fmaf(DY, Bv.y, w1);
            float w2b = 1.0f - w0b - w1b;
            float izb = fmaf(w1b, Bv.w, fmaf(w0b, Bv.z, e));
            bool okb  = (fminf(fminf(w0b, w1b), w2b) >= 0.0f) &&
                        (izb > 0.01f) && (izb < 10.0f);
            best1 = fmaxf(best1, okb ? izb : 0.0f);
        }

        unsigned* bb = &g_best[b * (IMG * IMG)];
        if (best0 > 0.0f) atomicMax(&bb[iy * IMG + ix],       __float_as_uint(best0));
        if (best1 > 0.0f) atomicMax(&bb[(iy + 8) * IMG + ix], __float_as_uint(best1));
        __syncthreads();
    }
}

// ---------------------------------------------------------------------------
// Kernel 4: convert max(inv_z) -> depth. Vectorized 4 px/thread.
// ---------------------------------------------------------------------------
__global__ void final_k(float* __restrict__ out, int npx4)
{
    int i = blockIdx.x * blockDim.x + threadIdx.x;
    if (i >= npx4) return;
    uint4 u = ((const uint4*)g_best)[i];
    float4 r;
    r.x = (u.x > 0u) ? (1.0f / __uint_as_float(u.x)) : FARP;
    r.y = (u.y > 0u) ? (1.0f / __uint_as_float(u.y)) : FARP;
    r.z = (u.z > 0u) ? (1.0f / __uint_as_float(u.z)) : FARP;
    r.w = (u.w > 0u) ? (1.0f / __uint_as_float(u.w)) : FARP;
    ((float4*)out)[i] = r;
}

// ---------------------------------------------------------------------------
extern "C" void kernel_launch(void* const* d_in, const int* in_sizes, int n_in,
                              void* d_out, int out_size)
{
    const float* verts = (const float*)d_in[0];
    const int*   faces = (const int*)d_in[1];
    float*       out   = (float*)d_out;

    int B = out_size / (IMG * IMG);
    if (B < 1) B = 1;
    int nv = in_sizes[0] / (3 * B);
    int nf = in_sizes[1] / (3 * B);
    int nvt = B * nv;
    int nft = B * nf;
    int npx = B * IMG * IMG;
    int npx4 = npx / 4;

    int initN = npx4 > nvt ? npx4 : nvt;
    init_k<<<(initN + 255) / 256, 256>>>(verts, nvt, npx4);
    face_k<<<(nft + FACE_T - 1) / FACE_T, FACE_T>>>(faces, nf, nv, B);
    rast_k<<<RASTB, 128>>>();
    final_k<<<(npx4 + 255) / 256, 256>>>(out, npx4);
}